// round 14
// baseline (speedup 1.0000x reference)
#include <cuda_runtime.h>
#include <math.h>

// ---------------- scratch (device globals; no mallocs) ----------------
__device__ __align__(16) float g_c1[2048*32*28*36];   // conv1 out (padded rows)
__device__ __align__(16) float g_c2[2048*64*13*13];   // conv2 out
__device__ __align__(16) float g_c3[2048*64*36];      // conv3 out (N,64,36)
__device__ __align__(16) float g_tok[2048*36*64];     // tokens (N,36,64)
__device__ __align__(16) float g_qkv[2048*36*192];    // qkv
__device__ __align__(16) float g_attn[2048*36*64];    // attention out (N,36,64)
__device__ __align__(16) float g_h2[2048*2304];       // residual -> FC input
__device__ __align__(16) float g_feat[2048*256];      // FC out
__device__ __align__(16) float g_gx[2048*384];        // input-side GRU gates
__device__ __align__(16) float g_hid[2048*128];       // GRU hidden per step
__device__ __align__(16) float g_w1f[4*32*32*2];      // conv1 B fragments (tf32 bits)
__device__ __align__(16) float g_w2f[8*64*32*2];      // conv2 B fragments (tf32 bits)
__device__ __align__(16) float g_w3t[576*64];
__device__ __align__(16) float g_whht[128*384];       // whh transposed [k][gate]

// ---------------- mma helpers ----------------
__device__ __forceinline__ void mma_tf32(float* d, const unsigned* a,
                                         unsigned b0, unsigned b1) {
    asm volatile(
        "mma.sync.aligned.m16n8k8.row.col.f32.tf32.tf32.f32 "
        "{%0,%1,%2,%3}, {%4,%5,%6,%7}, {%8,%9}, {%0,%1,%2,%3};"
        : "+f"(d[0]), "+f"(d[1]), "+f"(d[2]), "+f"(d[3])
        : "r"(a[0]), "r"(a[1]), "r"(a[2]), "r"(a[3]), "r"(b0), "r"(b1));
}
__device__ __forceinline__ unsigned to_tf32(float f) {
    unsigned r;
    asm("cvt.rna.tf32.f32 %0, %1;" : "=r"(r) : "f"(f));
    return r;
}

// ---------------- fused weight prep (packB + packB2 + 2 transposes) ----------
// grid 416 x 256 = 106496 threads, exact partition.
__global__ void k_prep(const float* __restrict__ c1w, const float* __restrict__ c2w,
                       const float* __restrict__ c3w, const float* __restrict__ whh) {
    int idx = blockIdx.x*256 + threadIdx.x;
    if (idx < 4096) {
        int i = idx;
        int lane = i & 31;
        int kstep = (i >> 5) & 31;
        int j = i >> 10;
        int co = j*8 + (lane >> 2);
        int k0 = kstep*8 + (lane & 3);
        g_w1f[i*2]   = __uint_as_float(to_tf32(c1w[co*256 + k0]));
        g_w1f[i*2+1] = __uint_as_float(to_tf32(c1w[co*256 + k0 + 4]));
    } else if (idx < 4096 + 16384) {
        int i = idx - 4096;
        int lane = i & 31;
        int kstep = (i >> 5) & 63;
        int j = i >> 11;
        int co = j*8 + (lane >> 2);
        int q  = lane & 3;
        int cin = kstep >> 1, s = kstep & 1;
        int base = co*512 + cin*16 + (2*s)*4 + q;
        g_w2f[i*2]   = __uint_as_float(to_tf32(c2w[base]));
        g_w2f[i*2+1] = __uint_as_float(to_tf32(c2w[base + 4]));
    } else if (idx < 4096 + 16384 + 36864) {
        int i = idx - (4096 + 16384);
        int co = i / 576, k = i % 576;
        g_w3t[k*64 + co] = c3w[i];
    } else {
        int i = idx - (4096 + 16384 + 36864);
        int co = i / 128, k = i % 128;
        g_whht[k*384 + co] = whh[i];
    }
}

// ---------------- conv1 (tensor): (N,4,116,116) -> relu (N,32,28,28pad36) ------
__global__ void __launch_bounds__(128) k_conv1t(const float* __restrict__ x,
                                                const float* __restrict__ bias) {
    __shared__ __align__(16) float xs[4*20*116];   // 37120 B
    int n = blockIdx.y, bx = blockIdx.x;
    int tid = threadIdx.x;
    {
        int iy0 = 16*bx;
        for (int i = tid; i < 2320; i += 128) {
            int cin = i / 580;
            int rem = i - cin*580;
            int row = rem / 29, q = rem - row*29;
            float4 v = *(const float4*)(x + ((size_t)(n*4+cin)*116 + iy0 + row)*116 + 4*q);
            *(float4*)(xs + (cin*20 + row)*116 + 4*q) = v;
        }
    }
    __syncthreads();
    int w = tid >> 5, lane = tid & 31;
    int p = lane >> 2, kx = lane & 3;
    int oy = bx*4 + w;
    float acc[2][4][4] = {};
    #pragma unroll
    for (int cin = 0; cin < 4; cin++) {
        #pragma unroll
        for (int ky = 0; ky < 8; ky++) {
            const float* row = xs + (cin*20 + 4*w + ky)*116;
            int kstep = cin*8 + ky;
            unsigned a[2][4];
            #pragma unroll
            for (int t = 0; t < 2; t++) {
                int base = 48*t + 4*p + kx;
                a[t][0] = to_tf32(row[base]);
                a[t][1] = to_tf32(row[base + 32]);
                a[t][2] = to_tf32(row[base + 4]);
                a[t][3] = to_tf32(row[base + 36]);
            }
            const float* wb = g_w1f + (size_t)kstep*64 + lane*2;
            #pragma unroll
            for (int j = 0; j < 4; j++) {
                float2 b = *(const float2*)(wb + (size_t)j*2048);
                unsigned b0 = __float_as_uint(b.x), b1 = __float_as_uint(b.y);
                mma_tf32(acc[0][j], a[0], b0, b1);
                mma_tf32(acc[1][j], a[1], b0, b1);
            }
        }
    }
    #pragma unroll
    for (int j = 0; j < 4; j++) {
        int co = j*8 + 2*kx;
        float2 bv = *(const float2*)(bias + co);
        float* outp = g_c1 + ((size_t)(n*32+co)*28 + oy)*36;
        #pragma unroll
        for (int t = 0; t < 2; t++) {
            int ox0 = 12*t + p;
            int ox1 = ox0 + 8;
            if (t == 0 || ox0 >= 16) {
                float v0 = acc[t][j][0] + bv.x;
                float v1 = acc[t][j][1] + bv.y;
                outp[ox0]        = v0 > 0.f ? v0 : 0.f;
                outp[1008 + ox0] = v1 > 0.f ? v1 : 0.f;
            }
            {
                float v2 = acc[t][j][2] + bv.x;
                float v3 = acc[t][j][3] + bv.y;
                outp[ox1]        = v2 > 0.f ? v2 : 0.f;
                outp[1008 + ox1] = v3 > 0.f ? v3 : 0.f;
            }
        }
    }
}

// ---------------- conv2 (tensor): (N,32,28pad36) -> relu (N,64,13,13), k4 s2 ---
__global__ void __launch_bounds__(128) k_conv2t(const float* __restrict__ bias) {
    int w = threadIdx.x >> 5, lane = threadIdx.x & 31;
    int n  = blockIdx.y*4 + w;
    int oy = blockIdx.x;
    int p = lane >> 2, q = lane & 3;
    float acc[8][4] = {};
    const float* xbase = g_c1 + (size_t)n*32*1008 + 2*oy*36;
    #pragma unroll 4
    for (int cin = 0; cin < 32; cin++) {
        const float* xc = xbase + cin*1008;
        #pragma unroll
        for (int s = 0; s < 2; s++) {
            const float* row0 = xc + 2*s*36;
            const float* row1 = row0 + 36;
            unsigned a[4];
            a[0] = to_tf32(row0[2*p + q]);
            a[1] = to_tf32(row0[2*p + 16 + q]);
            a[2] = to_tf32(row1[2*p + q]);
            a[3] = to_tf32(row1[2*p + 16 + q]);
            int kstep = cin*2 + s;
            const float* wb = g_w2f + (size_t)kstep*64 + lane*2;
            #pragma unroll
            for (int j = 0; j < 8; j++) {
                float2 b = *(const float2*)(wb + (size_t)j*4096);
                mma_tf32(acc[j], a, __float_as_uint(b.x), __float_as_uint(b.y));
            }
        }
    }
    bool hi = (p + 8 < 13);
    #pragma unroll
    for (int j = 0; j < 8; j++) {
        int co = j*8 + 2*q;
        float2 bv = *(const float2*)(bias + co);
        float* o0 = g_c2 + ((size_t)(n*64+co)*13 + oy)*13;
        float v0 = acc[j][0] + bv.x;
        float v1 = acc[j][1] + bv.y;
        o0[p]       = v0 > 0.f ? v0 : 0.f;
        o0[169 + p] = v1 > 0.f ? v1 : 0.f;
        if (hi) {
            float v2 = acc[j][2] + bv.x;
            float v3 = acc[j][3] + bv.y;
            o0[p + 8]       = v2 > 0.f ? v2 : 0.f;
            o0[169 + p + 8] = v3 > 0.f ? v3 : 0.f;
        }
    }
}

// ---------------- conv3: (N,64,13,13) -> relu (N,64,6,6), k3 s2 ----------------
__global__ void k_conv3(const float* __restrict__ bias) {
    __shared__ float xs[64*169];   // 43.3 KB
    int n = blockIdx.x;
    int t = threadIdx.x;
    {
        const float4* src = (const float4*)(g_c2 + (size_t)n*10816);
        float4* dst = (float4*)xs;
        for (int i = t; i < 2704; i += 288) dst[i] = src[i];
    }
    __syncthreads();
    int sq = t % 18, cq = t / 18;
    int s0 = sq*2;
    int sy = s0/6, sx = s0%6;
    float acc[2][4] = {};
    #pragma unroll 4
    for (int cin = 0; cin < 64; cin++) {
        const float* xc = xs + cin*169;
        #pragma unroll
        for (int ky = 0; ky < 3; ky++) {
            const float* row = xc + (2*sy+ky)*13 + 2*sx;
            #pragma unroll
            for (int kx = 0; kx < 3; kx++) {
                float4 wv = *(const float4*)(g_w3t + ((cin*3+ky)*3+kx)*64 + 4*cq);
                float i0 = row[kx];
                float i1 = row[kx+2];
                acc[0][0] += i0*wv.x; acc[0][1] += i0*wv.y;
                acc[0][2] += i0*wv.z; acc[0][3] += i0*wv.w;
                acc[1][0] += i1*wv.x; acc[1][1] += i1*wv.y;
                acc[1][2] += i1*wv.z; acc[1][3] += i1*wv.w;
            }
        }
    }
    #pragma unroll
    for (int j = 0; j < 4; j++) {
        int co = cq*4 + j;
        float b = bias[co];
        #pragma unroll
        for (int i = 0; i < 2; i++) {
            float v = acc[i][j] + b;
            g_c3[(size_t)(n*64+co)*36 + s0 + i] = v > 0.f ? v : 0.f;
        }
    }
}

// ---------------- fused CBAM (channel + spatial) -> tokens (N,36,64) ----------
__global__ void __launch_bounds__(256) k_cbam(const float* __restrict__ fc1w,
                                              const float* __restrict__ fc2w,
                                              const float* __restrict__ spw) {
    __shared__ float sh[2304], pm[64], px[64], hsh[32], ca[64], m2[36], x2[36], ss[36];
    int n = blockIdx.x, t = threadIdx.x;
    for (int o = t; o < 2304; o += 256) sh[o] = g_c3[(size_t)n*2304 + o];
    __syncthreads();
    if (t < 64) {
        const float* p = sh + t*36;
        float sum = 0.f, mx = -1e30f;
        #pragma unroll
        for (int s = 0; s < 36; s++) { float v = p[s]; sum += v; mx = fmaxf(mx, v); }
        pm[t] = sum * (1.f/36.f); px[t] = mx;
    }
    __syncthreads();
    if (t < 32) {
        int k = t & 15;
        const float* src = (t < 16) ? pm : px;
        float a = 0.f;
        #pragma unroll
        for (int j = 0; j < 64; j++) a += fc1w[k*64+j]*src[j];
        hsh[t] = fmaxf(a, 0.f);
    }
    __syncthreads();
    if (t < 64) {
        float a = 0.f;
        #pragma unroll
        for (int k = 0; k < 16; k++) a += fc2w[t*16+k]*(hsh[k] + hsh[16+k]);
        ca[t] = 1.f/(1.f+expf(-a));
    }
    __syncthreads();
    for (int o = t; o < 2304; o += 256) sh[o] *= ca[o/36];
    __syncthreads();
    if (t < 36) {
        float sum = 0.f, mx = -1e30f;
        #pragma unroll
        for (int c = 0; c < 64; c++) { float v = sh[c*36+t]; sum += v; mx = fmaxf(mx, v); }
        m2[t] = sum*(1.f/64.f); x2[t] = mx;
    }
    __syncthreads();
    if (t < 36) {
        int sy = t/6, sx = t%6;
        float a = 0.f;
        for (int ky = 0; ky < 7; ky++) {
            int iy = sy + ky - 3; if (iy < 0 || iy >= 6) continue;
            for (int kx = 0; kx < 7; kx++) {
                int ix = sx + kx - 3; if (ix < 0 || ix >= 6) continue;
                a += spw[ky*7+kx]*m2[iy*6+ix] + spw[49+ky*7+kx]*x2[iy*6+ix];
            }
        }
        ss[t] = 1.f/(1.f+expf(-a));
    }
    __syncthreads();
    for (int o = t; o < 2304; o += 256) {
        int c = o/36, s = o%36;
        g_tok[((size_t)n*36 + s)*64 + c] = sh[o]*ss[s];
    }
}

// ---------------- SGEMM: 128x64 CTA tile, 8x4/thread, double-buffered --------
// Per kk: 3 LDS.128 (~8 crossbar-cyc) vs 32 FFMA (~16 pipe-cyc) -> FFMA-bound.
// Requires M%128==0, N%64==0, K%16==0.
// EPI=1: proj epilogue — C is g_h2 in (n, c*36+s) layout, += projb + g_tok residual.
template<int RELU, int BIAS, int EPI>
__global__ void __launch_bounds__(256) k_gemm(const float* __restrict__ A,
                                              const float* __restrict__ W,
                                              const float* __restrict__ bias,
                                              float* __restrict__ C,
                                              int M, int N, int K) {
    __shared__ float As[2][16][128], Ws[2][16][64];
    int m0 = blockIdx.x*128, n0 = blockIdx.y*64;
    int tid = threadIdx.x;
    int alr = tid >> 1, alk = (tid & 1) << 3;   // A: 128 rows x 2 half-chunks
    int wlr = tid >> 2, wlk = (tid & 3) << 2;   // W: 64 rows x 4 quarter-chunks
    int tx = tid & 15, ty = tid >> 4;           // thread tile: m=tx*8, n=ty*4
    float acc[8][4] = {};
    float4 a0, a1, w0;
    a0 = *(const float4*)(A + (size_t)(m0+alr)*K + alk);
    a1 = *(const float4*)(A + (size_t)(m0+alr)*K + alk + 4);
    w0 = *(const float4*)(W + (size_t)(n0+wlr)*K + wlk);
    As[0][alk  ][alr] = a0.x; As[0][alk+1][alr] = a0.y;
    As[0][alk+2][alr] = a0.z; As[0][alk+3][alr] = a0.w;
    As[0][alk+4][alr] = a1.x; As[0][alk+5][alr] = a1.y;
    As[0][alk+6][alr] = a1.z; As[0][alk+7][alr] = a1.w;
    Ws[0][wlk  ][wlr] = w0.x; Ws[0][wlk+1][wlr] = w0.y;
    Ws[0][wlk+2][wlr] = w0.z; Ws[0][wlk+3][wlr] = w0.w;
    int nch = K >> 4;
    for (int ch = 0; ch < nch; ch++) {
        __syncthreads();
        int cur = ch & 1;
        bool pf = (ch + 1 < nch);
        if (pf) {
            a0 = *(const float4*)(A + (size_t)(m0+alr)*K + (ch+1)*16 + alk);
            a1 = *(const float4*)(A + (size_t)(m0+alr)*K + (ch+1)*16 + alk + 4);
            w0 = *(const float4*)(W + (size_t)(n0+wlr)*K + (ch+1)*16 + wlk);
        }
        #pragma unroll
        for (int kk = 0; kk < 16; kk++) {
            float4 av0 = *(const float4*)&As[cur][kk][tx<<3];
            float4 av1 = *(const float4*)&As[cur][kk][(tx<<3) + 4];
            float4 wv  = *(const float4*)&Ws[cur][kk][ty<<2];
            float ar[8] = {av0.x, av0.y, av0.z, av0.w, av1.x, av1.y, av1.z, av1.w};
            float wr[4] = {wv.x, wv.y, wv.z, wv.w};
            #pragma unroll
            for (int i = 0; i < 8; i++)
                #pragma unroll
                for (int j = 0; j < 4; j++)
                    acc[i][j] += ar[i]*wr[j];
        }
        if (pf) {
            int nxt = cur ^ 1;
            As[nxt][alk  ][alr] = a0.x; As[nxt][alk+1][alr] = a0.y;
            As[nxt][alk+2][alr] = a0.z; As[nxt][alk+3][alr] = a0.w;
            As[nxt][alk+4][alr] = a1.x; As[nxt][alk+5][alr] = a1.y;
            As[nxt][alk+6][alr] = a1.z; As[nxt][alk+7][alr] = a1.w;
            Ws[nxt][wlk  ][wlr] = w0.x; Ws[nxt][wlk+1][wlr] = w0.y;
            Ws[nxt][wlk+2][wlr] = w0.z; Ws[nxt][wlk+3][wlr] = w0.w;
        }
    }
    if (EPI) {
        #pragma unroll
        for (int i = 0; i < 8; i++) {
            int m = m0 + (tx<<3) + i;
            int img = m / 36, s = m % 36;
            float4 tk = *(const float4*)(g_tok + (size_t)m*64 + n0 + (ty<<2));
            float tkv[4] = {tk.x, tk.y, tk.z, tk.w};
            #pragma unroll
            for (int j = 0; j < 4; j++) {
                int c = n0 + (ty<<2) + j;
                C[(size_t)img*2304 + c*36 + s] = acc[i][j] + bias[c] + tkv[j];
            }
        }
        return;
    }
    #pragma unroll
    for (int i = 0; i < 8; i++) {
        int m = m0 + (tx<<3) + i;
        #pragma unroll
        for (int j = 0; j < 4; j++) {
            int nn = n0 + (ty<<2) + j;
            float v = acc[i][j];
            if (BIAS) v += bias[nn];
            if (RELU) v = fmaxf(v, 0.f);
            C[(size_t)m*N + nn] = v;
        }
    }
}

// ---------------- attention: block = 2 images, 288 threads (img,head,tok) -----
__global__ void __launch_bounds__(288) k_attn() {
    __shared__ float ks[2][36][64], vs[2][36][64];
    int t = threadIdx.x;
    int n0 = blockIdx.x*2;
    for (int i = t; i < 2304; i += 288) {
        int img = i / 1152, rem = i - img*1152;
        int s = rem >> 5, q4 = rem & 31;
        float4 v = *(const float4*)(g_qkv + ((size_t)(n0+img)*36 + s)*192 + 64 + 4*q4);
        if (q4 < 16) *(float4*)&ks[img][s][4*q4] = v;
        else         *(float4*)&vs[img][s][4*(q4-16)] = v;
    }
    __syncthreads();
    int img = t / 144, r = t - img*144;
    int head = r / 36, tok = r - head*36;
    int n = n0 + img;
    float qr[16];
    {
        const float* qp = g_qkv + ((size_t)n*36 + tok)*192 + head*16;
        #pragma unroll
        for (int d4 = 0; d4 < 4; d4++) {
            float4 v = *(const float4*)(qp + 4*d4);
            qr[4*d4] = v.x; qr[4*d4+1] = v.y; qr[4*d4+2] = v.z; qr[4*d4+3] = v.w;
        }
    }
    float sc[36]; float mx = -1e30f;
    #pragma unroll
    for (int s2 = 0; s2 < 36; s2++) {
        const float* kp = &ks[img][s2][head*16];
        float a = 0.f;
        #pragma unroll
        for (int d = 0; d < 16; d++) a += qr[d]*kp[d];
        a *= 0.25f;
        sc[s2] = a; mx = fmaxf(mx, a);
    }
    float sum = 0.f;
    #pragma unroll
    for (int s2 = 0; s2 < 36; s2++) { float e = expf(sc[s2]-mx); sc[s2] = e; sum += e; }
    float inv = 1.f/sum;
    float o[16];
    #pragma unroll
    for (int d = 0; d < 16; d++) {
        float a = 0.f;
        #pragma unroll
        for (int s2 = 0; s2 < 36; s2++) a += sc[s2]*vs[img][s2][head*16+d];
        o[d] = a*inv;
    }
    float* dst = g_attn + ((size_t)n*36 + tok)*64 + head*16;
    #pragma unroll
    for (int d4 = 0; d4 < 4; d4++)
        *(float4*)(dst + 4*d4) = make_float4(o[4*d4], o[4*d4+1], o[4*d4+2], o[4*d4+3]);
}

// ---------------- masked GRU scan: 32 independent batch chains ----------------
__global__ void k_gru(const float* __restrict__ done, const float* __restrict__ h0,
                      const float* __restrict__ bhh) {
    int b = blockIdx.x, t = threadIdx.x;
    __shared__ float h_s[128], hm_s[128], gh_s[384];
    h_s[t] = h0[b*128 + t];
    __syncthreads();
    for (int step = 0; step < 64; step++) {
        float dt = done[step*32 + b];
        hm_s[t] = (1.f - dt)*h_s[t];
        __syncthreads();
        if (t < 96) {
            int g = t*4;
            float a0 = bhh[g], a1 = bhh[g+1], a2 = bhh[g+2], a3 = bhh[g+3];
            #pragma unroll 8
            for (int k = 0; k < 128; k++) {
                float hm = hm_s[k];
                float4 w = *(const float4*)(g_whht + k*384 + g);
                a0 += w.x*hm; a1 += w.y*hm; a2 += w.z*hm; a3 += w.w*hm;
            }
            gh_s[g] = a0; gh_s[g+1] = a1; gh_s[g+2] = a2; gh_s[g+3] = a3;
        }
        __syncthreads();
        int row = step*32 + b;
        float xr = g_gx[(size_t)row*384 + t];
        float xz = g_gx[(size_t)row*384 + 128 + t];
        float xn = g_gx[(size_t)row*384 + 256 + t];
        float hr = gh_s[t], hz = gh_s[128+t], hn = gh_s[256+t];
        float rg = 1.f/(1.f+expf(-(xr+hr)));
        float zg = 1.f/(1.f+expf(-(xz+hz)));
        float ng = tanhf(xn + rg*hn);
        float hnew = (1.f-zg)*ng + zg*hm_s[t];
        h_s[t] = hnew;
        g_hid[(size_t)row*128 + t] = hnew;
        __syncthreads();
    }
}

// ---------------- critic head: (2048,128) @ crw^T + crb ----------------
__global__ void k_critic(const float* __restrict__ crw, const float* __restrict__ crb,
                         float* __restrict__ out) {
    int warp = threadIdx.x >> 5, lane = threadIdx.x & 31;
    int row = blockIdx.x*8 + warp;
    const float4* h4 = (const float4*)(g_hid + (size_t)row*128);
    float4 hv = h4[lane];
    float4 wv = ((const float4*)crw)[lane];
    float s = hv.x*wv.x + hv.y*wv.y + hv.z*wv.z + hv.w*wv.w;
    #pragma unroll
    for (int o = 16; o; o >>= 1) s += __shfl_down_sync(0xffffffffu, s, o);
    if (lane == 0) out[row] = s + crb[0];
}

// ---------------- launch ----------------
extern "C" void kernel_launch(void* const* d_in, const int* in_sizes, int n_in,
                              void* d_out, int out_size) {
    const float* x    = (const float*)d_in[0];
    const float* done = (const float*)d_in[1];
    const float* gru0 = (const float*)d_in[2];
    const float* c1w  = (const float*)d_in[3];
    const float* c1b  = (const float*)d_in[4];
    const float* c2w  = (const float*)d_in[5];
    const float* c2b  = (const float*)d_in[6];
    const float* c3w  = (const float*)d_in[7];
    const float* c3b  = (const float*)d_in[8];
    const float* fc1w = (const float*)d_in[9];
    const float* fc2w = (const float*)d_in[10];
    const float* spw  = (const float*)d_in[11];
    const float* qkvw = (const float*)d_in[12];
    const float* projw= (const float*)d_in[13];
    const float* projb= (const float*)d_in[14];
    const float* fcw  = (const float*)d_in[15];
    const float* fcb  = (const float*)d_in[16];
    const float* wih  = (const float*)d_in[17];
    const float* whh  = (const float*)d_in[18];
    const float* bih  = (const float*)d_in[19];
    const float* bhh  = (const float*)d_in[20];
    const float* crw  = (const float*)d_in[21];
    const float* crb  = (const float*)d_in[22];
    float* out = (float*)d_out;

    float *p_tok, *p_qkv, *p_h2, *p_feat, *p_gx, *p_attn;
    cudaGetSymbolAddress((void**)&p_tok,  g_tok);
    cudaGetSymbolAddress((void**)&p_qkv,  g_qkv);
    cudaGetSymbolAddress((void**)&p_h2,   g_h2);
    cudaGetSymbolAddress((void**)&p_feat, g_feat);
    cudaGetSymbolAddress((void**)&p_gx,   g_gx);
    cudaGetSymbolAddress((void**)&p_attn, g_attn);

    // launch order: prep(1), conv1t(2), conv2t(3), conv3(4 -> profiled slot)
    k_prep<<<416, 256>>>(c1w, c2w, c3w, whh);
    k_conv1t<<<dim3(7, 2048), 128>>>(x, c1b);
    k_conv2t<<<dim3(13, 512), 128>>>(c2b);
    k_conv3<<<2048, 288>>>(c3b);

    // fused CBAM
    k_cbam<<<2048, 256>>>(fc1w, fc2w, spw);

    // spatial self-attention
    k_gemm<0,0,0><<<dim3(73728/128, 192/64), 256>>>(p_tok, qkvw, (const float*)0, p_qkv, 73728, 192, 64);
    k_attn<<<1024, 288>>>();
    k_gemm<0,0,1><<<dim3(73728/128, 1), 256>>>(p_attn, projw, projb, p_h2, 73728, 64, 64);

    // FC + GRU input gates
    k_gemm<1,1,0><<<dim3(2048/128, 256/64), 256>>>(p_h2, fcw, fcb, p_feat, 2048, 256, 2304);
    k_gemm<0,1,0><<<dim3(2048/128, 384/64), 256>>>(p_feat, wih, bih, p_gx, 2048, 384, 256);

    // GRU scan + critic
    k_gru<<<32, 128>>>(done, gru0, bhh);
    k_critic<<<2048/8, 256>>>(crw, crb, out);
}

// round 15
// speedup vs baseline: 1.0775x; 1.0775x over previous
#include <cuda_runtime.h>
#include <math.h>

// ---------------- scratch (device globals; no mallocs) ----------------
__device__ __align__(16) float g_c1[2048*32*28*36];   // conv1 out (padded rows)
__device__ __align__(16) float g_c2[2048*64*13*13];   // conv2 out
__device__ __align__(16) float g_c3[2048*64*36];      // conv3 out (N,64,36)
__device__ __align__(16) float g_tok[2048*36*64];     // tokens (N,36,64)
__device__ __align__(16) float g_qkv[2048*36*192];    // qkv
__device__ __align__(16) float g_attn[2048*36*64];    // attention out (N,36,64)
__device__ __align__(16) float g_h2[2048*2304];       // residual -> FC input
__device__ __align__(16) float g_feat[2048*256];      // FC out
__device__ __align__(16) float g_gx[2048*384];        // input-side GRU gates
__device__ __align__(16) float g_hid[2048*128];       // GRU hidden per step
__device__ __align__(16) float g_w1f[4*32*32*2];      // conv1 B fragments (tf32 bits)
__device__ __align__(16) float g_w2f[8*64*32*2];      // conv2 B fragments
__device__ __align__(16) float g_w3f[8*128*32*2];     // conv3 B fragments (K padded 1024)
__device__ __align__(16) float g_whht[128*384];       // whh transposed [k][gate]

// ---------------- mma helpers ----------------
__device__ __forceinline__ void mma_tf32(float* d, const unsigned* a,
                                         unsigned b0, unsigned b1) {
    asm volatile(
        "mma.sync.aligned.m16n8k8.row.col.f32.tf32.tf32.f32 "
        "{%0,%1,%2,%3}, {%4,%5,%6,%7}, {%8,%9}, {%0,%1,%2,%3};"
        : "+f"(d[0]), "+f"(d[1]), "+f"(d[2]), "+f"(d[3])
        : "r"(a[0]), "r"(a[1]), "r"(a[2]), "r"(a[3]), "r"(b0), "r"(b1));
}
__device__ __forceinline__ unsigned to_tf32(float f) {
    unsigned r;
    asm("cvt.rna.tf32.f32 %0, %1;" : "=r"(r) : "f"(f));
    return r;
}

// ---------------- fused weight prep ----------
// partition: w1f 4096 | w2f 16384 | w3f 32768 | whht 49152 = 102400 = 400*256
__global__ void k_prep(const float* __restrict__ c1w, const float* __restrict__ c2w,
                       const float* __restrict__ c3w, const float* __restrict__ whh) {
    int idx = blockIdx.x*256 + threadIdx.x;
    if (idx < 4096) {
        int i = idx;
        int lane = i & 31;
        int kstep = (i >> 5) & 31;
        int j = i >> 10;
        int co = j*8 + (lane >> 2);
        int k0 = kstep*8 + (lane & 3);
        g_w1f[i*2]   = __uint_as_float(to_tf32(c1w[co*256 + k0]));
        g_w1f[i*2+1] = __uint_as_float(to_tf32(c1w[co*256 + k0 + 4]));
    } else if (idx < 4096 + 16384) {
        int i = idx - 4096;
        int lane = i & 31;
        int kstep = (i >> 5) & 63;
        int j = i >> 11;
        int co = j*8 + (lane >> 2);
        int q  = lane & 3;
        int cin = kstep >> 1, s = kstep & 1;
        int base = co*512 + cin*16 + (2*s)*4 + q;
        g_w2f[i*2]   = __uint_as_float(to_tf32(c2w[base]));
        g_w2f[i*2+1] = __uint_as_float(to_tf32(c2w[base + 4]));
    } else if (idx < 4096 + 16384 + 32768) {
        // conv3 fragments: kstep = cin*2+s (128); pos = s*8 + q (+4); pos>=9 -> 0
        int i = idx - (4096 + 16384);
        int lane = i & 31;
        int kstep = (i >> 5) & 127;
        int j = i >> 12;                 // 0..7
        int co = j*8 + (lane >> 2);
        int q  = lane & 3;
        int cin = kstep >> 1, s = kstep & 1;
        int pos0 = s*8 + q, pos1 = pos0 + 4;
        float v0 = (pos0 < 9) ? c3w[co*576 + cin*9 + pos0] : 0.f;
        float v1 = (pos1 < 9) ? c3w[co*576 + cin*9 + pos1] : 0.f;
        g_w3f[i*2]   = __uint_as_float(to_tf32(v0));
        g_w3f[i*2+1] = __uint_as_float(to_tf32(v1));
    } else {
        int i = idx - (4096 + 16384 + 32768);
        int co = i / 128, k = i % 128;
        g_whht[k*384 + co] = whh[i];
    }
}

// ---------------- conv1 (tensor): (N,4,116,116) -> relu (N,32,28,28pad36) ------
__global__ void __launch_bounds__(128) k_conv1t(const float* __restrict__ x,
                                                const float* __restrict__ bias) {
    __shared__ __align__(16) float xs[4*20*116];   // 37120 B
    int n = blockIdx.y, bx = blockIdx.x;
    int tid = threadIdx.x;
    {
        int iy0 = 16*bx;
        for (int i = tid; i < 2320; i += 128) {
            int cin = i / 580;
            int rem = i - cin*580;
            int row = rem / 29, q = rem - row*29;
            float4 v = *(const float4*)(x + ((size_t)(n*4+cin)*116 + iy0 + row)*116 + 4*q);
            *(float4*)(xs + (cin*20 + row)*116 + 4*q) = v;
        }
    }
    __syncthreads();
    int w = tid >> 5, lane = tid & 31;
    int p = lane >> 2, kx = lane & 3;
    int oy = bx*4 + w;
    float acc[2][4][4] = {};
    #pragma unroll
    for (int cin = 0; cin < 4; cin++) {
        #pragma unroll
        for (int ky = 0; ky < 8; ky++) {
            const float* row = xs + (cin*20 + 4*w + ky)*116;
            int kstep = cin*8 + ky;
            unsigned a[2][4];
            #pragma unroll
            for (int t = 0; t < 2; t++) {
                int base = 48*t + 4*p + kx;
                a[t][0] = to_tf32(row[base]);
                a[t][1] = to_tf32(row[base + 32]);
                a[t][2] = to_tf32(row[base + 4]);
                a[t][3] = to_tf32(row[base + 36]);
            }
            const float* wb = g_w1f + (size_t)kstep*64 + lane*2;
            #pragma unroll
            for (int j = 0; j < 4; j++) {
                float2 b = *(const float2*)(wb + (size_t)j*2048);
                unsigned b0 = __float_as_uint(b.x), b1 = __float_as_uint(b.y);
                mma_tf32(acc[0][j], a[0], b0, b1);
                mma_tf32(acc[1][j], a[1], b0, b1);
            }
        }
    }
    #pragma unroll
    for (int j = 0; j < 4; j++) {
        int co = j*8 + 2*kx;
        float2 bv = *(const float2*)(bias + co);
        float* outp = g_c1 + ((size_t)(n*32+co)*28 + oy)*36;
        #pragma unroll
        for (int t = 0; t < 2; t++) {
            int ox0 = 12*t + p;
            int ox1 = ox0 + 8;
            if (t == 0 || ox0 >= 16) {
                float v0 = acc[t][j][0] + bv.x;
                float v1 = acc[t][j][1] + bv.y;
                outp[ox0]        = v0 > 0.f ? v0 : 0.f;
                outp[1008 + ox0] = v1 > 0.f ? v1 : 0.f;
            }
            {
                float v2 = acc[t][j][2] + bv.x;
                float v3 = acc[t][j][3] + bv.y;
                outp[ox1]        = v2 > 0.f ? v2 : 0.f;
                outp[1008 + ox1] = v3 > 0.f ? v3 : 0.f;
            }
        }
    }
}

// ---------------- conv2 (tensor): (N,32,28pad36) -> relu (N,64,13,13), k4 s2 ---
__global__ void __launch_bounds__(128) k_conv2t(const float* __restrict__ bias) {
    int w = threadIdx.x >> 5, lane = threadIdx.x & 31;
    int n  = blockIdx.y*4 + w;
    int oy = blockIdx.x;
    int p = lane >> 2, q = lane & 3;
    float acc[8][4] = {};
    const float* xbase = g_c1 + (size_t)n*32*1008 + 2*oy*36;
    #pragma unroll 4
    for (int cin = 0; cin < 32; cin++) {
        const float* xc = xbase + cin*1008;
        #pragma unroll
        for (int s = 0; s < 2; s++) {
            const float* row0 = xc + 2*s*36;
            const float* row1 = row0 + 36;
            unsigned a[4];
            a[0] = to_tf32(row0[2*p + q]);
            a[1] = to_tf32(row0[2*p + 16 + q]);
            a[2] = to_tf32(row1[2*p + q]);
            a[3] = to_tf32(row1[2*p + 16 + q]);
            int kstep = cin*2 + s;
            const float* wb = g_w2f + (size_t)kstep*64 + lane*2;
            #pragma unroll
            for (int j = 0; j < 8; j++) {
                float2 b = *(const float2*)(wb + (size_t)j*4096);
                mma_tf32(acc[j], a, __float_as_uint(b.x), __float_as_uint(b.y));
            }
        }
    }
    bool hi = (p + 8 < 13);
    #pragma unroll
    for (int j = 0; j < 8; j++) {
        int co = j*8 + 2*q;
        float2 bv = *(const float2*)(bias + co);
        float* o0 = g_c2 + ((size_t)(n*64+co)*13 + oy)*13;
        float v0 = acc[j][0] + bv.x;
        float v1 = acc[j][1] + bv.y;
        o0[p]       = v0 > 0.f ? v0 : 0.f;
        o0[169 + p] = v1 > 0.f ? v1 : 0.f;
        if (hi) {
            float v2 = acc[j][2] + bv.x;
            float v3 = acc[j][3] + bv.y;
            o0[p + 8]       = v2 > 0.f ? v2 : 0.f;
            o0[169 + p + 8] = v3 > 0.f ? v3 : 0.f;
        }
    }
}

// ---------------- conv3 (tensor): (N,64,13,13) -> relu (N,64,6,6), k3 s2 -------
// Warp = one m16 tile of one image (3 tiles/image, rows = spatial 0..35, tails
// clamped & discarded — MMA row m depends only on A row m). N=64 as 8 n8 tiles.
// K = 64 cin x (9 padded to 16) = 1024 as 128 k8-steps; padded positions are
// zero in the B fragments so any A garbage there contributes 0.
__global__ void __launch_bounds__(128) k_conv3t(const float* __restrict__ bias) {
    int w = threadIdx.x >> 5, lane = threadIdx.x & 31;
    int gt = blockIdx.x*4 + w;          // 0..6143
    int n = gt / 3, tile = gt - 3*n;
    int p = lane >> 2, q = lane & 3;
    // per-thread spatial rows (clamped for address safety)
    int s_lo = tile*16 + p;  bool v_lo = (s_lo < 36); int sc_lo = v_lo ? s_lo : 35;
    int s_hi = s_lo + 8;     bool v_hi = (s_hi < 36); int sc_hi = v_hi ? s_hi : 35;
    int base_lo = (sc_lo/6)*26 + (sc_lo%6)*2;   // 2*sy*13 + 2*sx
    int base_hi = (sc_hi/6)*26 + (sc_hi%6)*2;
    // kernel-position offsets for this lane: pos q, q+4 (s=0); pos 8 (s=1, q==0)
    int o0 = (q/3)*13 + (q%3);
    int o1 = ((q+4)/3)*13 + ((q+4)%3);
    bool v2 = (q == 0);                  // pos 8 = (ky=2,kx=2) -> offset 28
    float acc[8][4] = {};
    const float* cbase = g_c2 + (size_t)n*10816;
    #pragma unroll 4
    for (int cin = 0; cin < 64; cin++) {
        const float* c = cbase + cin*169;
        unsigned a[4];
        a[0] = to_tf32(c[base_lo + o0]);
        a[1] = to_tf32(c[base_hi + o0]);
        a[2] = to_tf32(c[base_lo + o1]);
        a[3] = to_tf32(c[base_hi + o1]);
        const float* wb = g_w3f + (size_t)(cin*2)*64 + lane*2;
        #pragma unroll
        for (int j = 0; j < 8; j++) {
            float2 b = *(const float2*)(wb + (size_t)j*8192);
            mma_tf32(acc[j], a, __float_as_uint(b.x), __float_as_uint(b.y));
        }
        a[0] = v2 ? to_tf32(c[base_lo + 28]) : 0u;
        a[1] = v2 ? to_tf32(c[base_hi + 28]) : 0u;
        a[2] = 0u; a[3] = 0u;
        const float* wb2 = wb + 64;
        #pragma unroll
        for (int j = 0; j < 8; j++) {
            float2 b = *(const float2*)(wb2 + (size_t)j*8192);
            mma_tf32(acc[j], a, __float_as_uint(b.x), __float_as_uint(b.y));
        }
    }
    #pragma unroll
    for (int j = 0; j < 8; j++) {
        int co = j*8 + 2*q;
        float2 bv = *(const float2*)(bias + co);
        float* o0p = g_c3 + (size_t)(n*64+co)*36;
        if (v_lo) {
            float a0 = acc[j][0] + bv.x;
            float a1 = acc[j][1] + bv.y;
            o0p[s_lo]      = a0 > 0.f ? a0 : 0.f;
            o0p[36 + s_lo] = a1 > 0.f ? a1 : 0.f;
        }
        if (v_hi) {
            float a2 = acc[j][2] + bv.x;
            float a3 = acc[j][3] + bv.y;
            o0p[s_hi]      = a2 > 0.f ? a2 : 0.f;
            o0p[36 + s_hi] = a3 > 0.f ? a3 : 0.f;
        }
    }
}

// ---------------- fused CBAM (channel + spatial) -> tokens (N,36,64) ----------
__global__ void __launch_bounds__(256) k_cbam(const float* __restrict__ fc1w,
                                              const float* __restrict__ fc2w,
                                              const float* __restrict__ spw) {
    __shared__ float sh[2304], pm[64], px[64], hsh[32], ca[64], m2[36], x2[36], ss[36];
    int n = blockIdx.x, t = threadIdx.x;
    for (int o = t; o < 2304; o += 256) sh[o] = g_c3[(size_t)n*2304 + o];
    __syncthreads();
    if (t < 64) {
        const float* p = sh + t*36;
        float sum = 0.f, mx = -1e30f;
        #pragma unroll
        for (int s = 0; s < 36; s++) { float v = p[s]; sum += v; mx = fmaxf(mx, v); }
        pm[t] = sum * (1.f/36.f); px[t] = mx;
    }
    __syncthreads();
    if (t < 32) {
        int k = t & 15;
        const float* src = (t < 16) ? pm : px;
        float a = 0.f;
        #pragma unroll
        for (int j = 0; j < 64; j++) a += fc1w[k*64+j]*src[j];
        hsh[t] = fmaxf(a, 0.f);
    }
    __syncthreads();
    if (t < 64) {
        float a = 0.f;
        #pragma unroll
        for (int k = 0; k < 16; k++) a += fc2w[t*16+k]*(hsh[k] + hsh[16+k]);
        ca[t] = 1.f/(1.f+expf(-a));
    }
    __syncthreads();
    for (int o = t; o < 2304; o += 256) sh[o] *= ca[o/36];
    __syncthreads();
    if (t < 36) {
        float sum = 0.f, mx = -1e30f;
        #pragma unroll
        for (int c = 0; c < 64; c++) { float v = sh[c*36+t]; sum += v; mx = fmaxf(mx, v); }
        m2[t] = sum*(1.f/64.f); x2[t] = mx;
    }
    __syncthreads();
    if (t < 36) {
        int sy = t/6, sx = t%6;
        float a = 0.f;
        for (int ky = 0; ky < 7; ky++) {
            int iy = sy + ky - 3; if (iy < 0 || iy >= 6) continue;
            for (int kx = 0; kx < 7; kx++) {
                int ix = sx + kx - 3; if (ix < 0 || ix >= 6) continue;
                a += spw[ky*7+kx]*m2[iy*6+ix] + spw[49+ky*7+kx]*x2[iy*6+ix];
            }
        }
        ss[t] = 1.f/(1.f+expf(-a));
    }
    __syncthreads();
    for (int o = t; o < 2304; o += 256) {
        int c = o/36, s = o%36;
        g_tok[((size_t)n*36 + s)*64 + c] = sh[o]*ss[s];
    }
}

// ---------------- SGEMM, 64x64 tile, double-buffered (round-12 version) -------
// EPI=1: proj epilogue — C is g_h2 in (n, c*36+s) layout, += projb + g_tok residual.
template<int RELU, int BIAS, int EPI>
__global__ void k_gemm(const float* __restrict__ A, const float* __restrict__ W,
                       const float* __restrict__ bias, float* __restrict__ C,
                       int M, int N, int K) {
    __shared__ float As[2][16][64], Ws[2][16][64];
    int m0 = blockIdx.x*64, n0 = blockIdx.y*64;
    int tid = threadIdx.x;
    int lr = tid >> 2, lk = (tid & 3) << 2;
    int tx = tid & 15, ty = tid >> 4;
    float acc[4][4] = {};
    float4 a = *(const float4*)(A + (size_t)(m0+lr)*K + lk);
    float4 w = *(const float4*)(W + (size_t)(n0+lr)*K + lk);
    As[0][lk  ][lr] = a.x; As[0][lk+1][lr] = a.y; As[0][lk+2][lr] = a.z; As[0][lk+3][lr] = a.w;
    Ws[0][lk  ][lr] = w.x; Ws[0][lk+1][lr] = w.y; Ws[0][lk+2][lr] = w.z; Ws[0][lk+3][lr] = w.w;
    int nch = K >> 4;
    for (int ch = 0; ch < nch; ch++) {
        __syncthreads();
        int cur = ch & 1;
        bool pf = (ch + 1 < nch);
        if (pf) {
            a = *(const float4*)(A + (size_t)(m0+lr)*K + (ch+1)*16 + lk);
            w = *(const float4*)(W + (size_t)(n0+lr)*K + (ch+1)*16 + lk);
        }
        #pragma unroll
        for (int kk = 0; kk < 16; kk++) {
            float4 av = *(const float4*)&As[cur][kk][tx<<2];
            float4 wv = *(const float4*)&Ws[cur][kk][ty<<2];
            float ar[4] = {av.x, av.y, av.z, av.w};
            float wr[4] = {wv.x, wv.y, wv.z, wv.w};
            #pragma unroll
            for (int i = 0; i < 4; i++)
                #pragma unroll
                for (int j = 0; j < 4; j++)
                    acc[i][j] += ar[i]*wr[j];
        }
        if (pf) {
            int nxt = cur ^ 1;
            As[nxt][lk  ][lr] = a.x; As[nxt][lk+1][lr] = a.y;
            As[nxt][lk+2][lr] = a.z; As[nxt][lk+3][lr] = a.w;
            Ws[nxt][lk  ][lr] = w.x; Ws[nxt][lk+1][lr] = w.y;
            Ws[nxt][lk+2][lr] = w.z; Ws[nxt][lk+3][lr] = w.w;
        }
    }
    if (EPI) {
        #pragma unroll
        for (int i = 0; i < 4; i++) {
            int m = m0 + (tx<<2) + i;
            int img = m / 36, s = m % 36;
            float4 tk = *(const float4*)(g_tok + (size_t)m*64 + n0 + (ty<<2));
            float tkv[4] = {tk.x, tk.y, tk.z, tk.w};
            #pragma unroll
            for (int j = 0; j < 4; j++) {
                int c = n0 + (ty<<2) + j;
                C[(size_t)img*2304 + c*36 + s] = acc[i][j] + bias[c] + tkv[j];
            }
        }
        return;
    }
    #pragma unroll
    for (int i = 0; i < 4; i++) {
        int m = m0 + (tx<<2) + i;
        #pragma unroll
        for (int j = 0; j < 4; j++) {
            int nn = n0 + (ty<<2) + j;
            float v = acc[i][j];
            if (BIAS) v += bias[nn];
            if (RELU) v = fmaxf(v, 0.f);
            C[(size_t)m*N + nn] = v;
        }
    }
}

// ---------------- attention: block = 2 images, 288 threads (img,head,tok) -----
__global__ void __launch_bounds__(288) k_attn() {
    __shared__ float ks[2][36][64], vs[2][36][64];
    int t = threadIdx.x;
    int n0 = blockIdx.x*2;
    for (int i = t; i < 2304; i += 288) {
        int img = i / 1152, rem = i - img*1152;
        int s = rem >> 5, q4 = rem & 31;
        float4 v = *(const float4*)(g_qkv + ((size_t)(n0+img)*36 + s)*192 + 64 + 4*q4);
        if (q4 < 16) *(float4*)&ks[img][s][4*q4] = v;
        else         *(float4*)&vs[img][s][4*(q4-16)] = v;
    }
    __syncthreads();
    int img = t / 144, r = t - img*144;
    int head = r / 36, tok = r - head*36;
    int n = n0 + img;
    float qr[16];
    {
        const float* qp = g_qkv + ((size_t)n*36 + tok)*192 + head*16;
        #pragma unroll
        for (int d4 = 0; d4 < 4; d4++) {
            float4 v = *(const float4*)(qp + 4*d4);
            qr[4*d4] = v.x; qr[4*d4+1] = v.y; qr[4*d4+2] = v.z; qr[4*d4+3] = v.w;
        }
    }
    float sc[36]; float mx = -1e30f;
    #pragma unroll
    for (int s2 = 0; s2 < 36; s2++) {
        const float* kp = &ks[img][s2][head*16];
        float a = 0.f;
        #pragma unroll
        for (int d = 0; d < 16; d++) a += qr[d]*kp[d];
        a *= 0.25f;
        sc[s2] = a; mx = fmaxf(mx, a);
    }
    float sum = 0.f;
    #pragma unroll
    for (int s2 = 0; s2 < 36; s2++) { float e = expf(sc[s2]-mx); sc[s2] = e; sum += e; }
    float inv = 1.f/sum;
    float o[16];
    #pragma unroll
    for (int d = 0; d < 16; d++) {
        float a = 0.f;
        #pragma unroll
        for (int s2 = 0; s2 < 36; s2++) a += sc[s2]*vs[img][s2][head*16+d];
        o[d] = a*inv;
    }
    float* dst = g_attn + ((size_t)n*36 + tok)*64 + head*16;
    #pragma unroll
    for (int d4 = 0; d4 < 4; d4++)
        *(float4*)(dst + 4*d4) = make_float4(o[4*d4], o[4*d4+1], o[4*d4+2], o[4*d4+3]);
}

// ---------------- masked GRU scan: 32 independent batch chains ----------------
__global__ void k_gru(const float* __restrict__ done, const float* __restrict__ h0,
                      const float* __restrict__ bhh) {
    int b = blockIdx.x, t = threadIdx.x;
    __shared__ float h_s[128], hm_s[128], gh_s[384];
    h_s[t] = h0[b*128 + t];
    __syncthreads();
    for (int step = 0; step < 64; step++) {
        float dt = done[step*32 + b];
        hm_s[t] = (1.f - dt)*h_s[t];
        __syncthreads();
        if (t < 96) {
            int g = t*4;
            float a0 = bhh[g], a1 = bhh[g+1], a2 = bhh[g+2], a3 = bhh[g+3];
            #pragma unroll 8
            for (int k = 0; k < 128; k++) {
                float hm = hm_s[k];
                float4 w = *(const float4*)(g_whht + k*384 + g);
                a0 += w.x*hm; a1 += w.y*hm; a2 += w.z*hm; a3 += w.w*hm;
            }
            gh_s[g] = a0; gh_s[g+1] = a1; gh_s[g+2] = a2; gh_s[g+3] = a3;
        }
        __syncthreads();
        int row = step*32 + b;
        float xr = g_gx[(size_t)row*384 + t];
        float xz = g_gx[(size_t)row*384 + 128 + t];
        float xn = g_gx[(size_t)row*384 + 256 + t];
        float hr = gh_s[t], hz = gh_s[128+t], hn = gh_s[256+t];
        float rg = 1.f/(1.f+expf(-(xr+hr)));
        float zg = 1.f/(1.f+expf(-(xz+hz)));
        float ng = tanhf(xn + rg*hn);
        float hnew = (1.f-zg)*ng + zg*hm_s[t];
        h_s[t] = hnew;
        g_hid[(size_t)row*128 + t] = hnew;
        __syncthreads();
    }
}

// ---------------- critic head: (2048,128) @ crw^T + crb ----------------
__global__ void k_critic(const float* __restrict__ crw, const float* __restrict__ crb,
                         float* __restrict__ out) {
    int warp = threadIdx.x >> 5, lane = threadIdx.x & 31;
    int row = blockIdx.x*8 + warp;
    const float4* h4 = (const float4*)(g_hid + (size_t)row*128);
    float4 hv = h4[lane];
    float4 wv = ((const float4*)crw)[lane];
    float s = hv.x*wv.x + hv.y*wv.y + hv.z*wv.z + hv.w*wv.w;
    #pragma unroll
    for (int o = 16; o; o >>= 1) s += __shfl_down_sync(0xffffffffu, s, o);
    if (lane == 0) out[row] = s + crb[0];
}

// ---------------- launch ----------------
extern "C" void kernel_launch(void* const* d_in, const int* in_sizes, int n_in,
                              void* d_out, int out_size) {
    const float* x    = (const float*)d_in[0];
    const float* done = (const float*)d_in[1];
    const float* gru0 = (const float*)d_in[2];
    const float* c1w  = (const float*)d_in[3];
    const float* c1b  = (const float*)d_in[4];
    const float* c2w  = (const float*)d_in[5];
    const float* c2b  = (const float*)d_in[6];
    const float* c3w  = (const float*)d_in[7];
    const float* c3b  = (const float*)d_in[8];
    const float* fc1w = (const float*)d_in[9];
    const float* fc2w = (const float*)d_in[10];
    const float* spw  = (const float*)d_in[11];
    const float* qkvw = (const float*)d_in[12];
    const float* projw= (const float*)d_in[13];
    const float* projb= (const float*)d_in[14];
    const float* fcw  = (const float*)d_in[15];
    const float* fcb  = (const float*)d_in[16];
    const float* wih  = (const float*)d_in[17];
    const float* whh  = (const float*)d_in[18];
    const float* bih  = (const float*)d_in[19];
    const float* bhh  = (const float*)d_in[20];
    const float* crw  = (const float*)d_in[21];
    const float* crb  = (const float*)d_in[22];
    float* out = (float*)d_out;

    float *p_tok, *p_qkv, *p_h2, *p_feat, *p_gx, *p_attn;
    cudaGetSymbolAddress((void**)&p_tok,  g_tok);
    cudaGetSymbolAddress((void**)&p_qkv,  g_qkv);
    cudaGetSymbolAddress((void**)&p_h2,   g_h2);
    cudaGetSymbolAddress((void**)&p_feat, g_feat);
    cudaGetSymbolAddress((void**)&p_gx,   g_gx);
    cudaGetSymbolAddress((void**)&p_attn, g_attn);

    // launch order: prep(1), conv1t(2), conv2t(3), conv3t(4 -> profiled slot)
    k_prep<<<400, 256>>>(c1w, c2w, c3w, whh);
    k_conv1t<<<dim3(7, 2048), 128>>>(x, c1b);
    k_conv2t<<<dim3(13, 512), 128>>>(c2b);
    k_conv3t<<<1536, 128>>>(c3b);

    // fused CBAM
    k_cbam<<<2048, 256>>>(fc1w, fc2w, spw);

    // spatial self-attention
    k_gemm<0,0,0><<<dim3(73728/64, 192/64), 256>>>(p_tok, qkvw, (const float*)0, p_qkv, 73728, 192, 64);
    k_attn<<<1024, 288>>>();
    k_gemm<0,0,1><<<dim3(73728/64, 1), 256>>>(p_attn, projw, projb, p_h2, 73728, 64, 64);

    // FC + GRU input gates
    k_gemm<1,1,0><<<dim3(2048/64, 256/64), 256>>>(p_h2, fcw, fcb, p_feat, 2048, 256, 2304);
    k_gemm<0,1,0><<<dim3(2048/64, 384/64), 256>>>(p_feat, wih, bih, p_gx, 2048, 384, 256);

    // GRU scan + critic
    k_gru<<<32, 128>>>(done, gru0, bhh);
    k_critic<<<2048/8, 256>>>(crw, crb, out);
}